// round 15
// baseline (speedup 1.0000x reference)
#include <cuda_runtime.h>

// Volume rendering (NeRF-style) on GB300 — FINAL (R5 config, best measured).
//
// Session evidence (DRAM% / wall us):
//   R1  strided rgb            87.8 / 98.1
//   R2  unit-stride rgb+smem   87.5 / 98.5   (access pattern irrelevant)
//   R5  R1 + __ldcs hints      88.8 / 96.3   <- WIN, this kernel
//   R6  2 rays/warp            89.0 / 97.0   (MLP depth: neutral)
//   R7  persistent dbl-buf     85.1 / 102.5  (occ collapse: falsified)
//   R8  2 rays + min-blocks 7  86.2 / 98.8   (reg squeeze de-batches loads)
//   R11 = R5 source re-run     88.2 / 97.8   (same-binary noise ~±1 us)
// Conclusion: ~88.5% DRAM busy (~7.0 TB/s) is the ceiling for this 674 MB
// read-once stream (B300 path-independent LTS cap). All structural levers
// tested; .cs streaming hints are the only reproducible win.
//
// Inputs (metadata order): rgb [N,128,3] f32, density [N,128,1] f32,
//                          distances [N,128] f32. Output: [N,3] f32.
//
// One warp per ray; 4 consecutive samples per lane.
//   delta_i  = t_{i+1} - t_i   (last sample: 1e10)
//   omega_i  = exp(-density_i * delta_i)      (= 1 - alpha_i)
//   T_i      = exclusive cumprod(omega)       (warp shfl scan)
//   weight_i = (1 - omega_i) * T_i
//   out      = sum_i weight_i * rgb_i

#ifndef FULL_MASK
#define FULL_MASK 0xffffffffu
#endif

static constexpr int N_SAMPLES = 128;
static constexpr float FAR_DELTA = 1e10f;

__global__ void __launch_bounds__(256, 8)
volrend_kernel(const float* __restrict__ rgb,
               const float* __restrict__ density,
               const float* __restrict__ dist,
               float* __restrict__ out,
               int n_rays)
{
    const int warp_id = (blockIdx.x * blockDim.x + threadIdx.x) >> 5;
    const int lane    = threadIdx.x & 31;
    if (warp_id >= n_rays) return;

    const long base = (long)warp_id * N_SAMPLES;

    // ---- coalesced streaming loads: 4 samples per lane ----
    const float4 d4 = __ldcs(reinterpret_cast<const float4*>(dist    + base) + lane);
    const float4 s4 = __ldcs(reinterpret_cast<const float4*>(density + base) + lane);
    const float4* rgb4 = reinterpret_cast<const float4*>(rgb + base * 3) + lane * 3;
    const float4 c0 = __ldcs(rgb4 + 0);
    const float4 c1 = __ldcs(rgb4 + 1);
    const float4 c2 = __ldcs(rgb4 + 2);

    // ---- deltas (next lane's first distance via shfl) ----
    const float d_next = __shfl_down_sync(FULL_MASK, d4.x, 1);
    const float dl0 = d4.y - d4.x;
    const float dl1 = d4.z - d4.y;
    const float dl2 = d4.w - d4.z;
    const float dl3 = (lane == 31) ? FAR_DELTA : (d_next - d4.w);

    // ---- omega = exp(-sigma * delta) = 1 - alpha ----
    const float w0 = __expf(-s4.x * dl0);
    const float w1 = __expf(-s4.y * dl1);
    const float w2 = __expf(-s4.z * dl2);
    const float w3 = __expf(-s4.w * dl3);

    // ---- exclusive cumprod across the warp ----
    const float p = w0 * w1 * w2 * w3;     // this lane's full product
    float incl = p;                        // inclusive scan of lane products
    #pragma unroll
    for (int off = 1; off < 32; off <<= 1) {
        const float v = __shfl_up_sync(FULL_MASK, incl, off);
        if (lane >= off) incl *= v;
    }
    float T = __shfl_up_sync(FULL_MASK, incl, 1);   // exclusive: prev lane's inclusive
    if (lane == 0) T = 1.0f;

    // ---- local weights: T walks through this lane's 4 samples ----
    const float t0 = T;
    const float t1 = t0 * w0;
    const float t2 = t1 * w1;
    const float t3 = t2 * w2;
    const float wt0 = t0 - t1;             // = alpha0 * T0
    const float wt1 = t1 - t2;
    const float wt2 = t2 - t3;
    const float wt3 = t3 * (1.0f - w3);

    // rgb layout per lane: s0=(c0.x,c0.y,c0.z) s1=(c0.w,c1.x,c1.y)
    //                      s2=(c1.z,c1.w,c2.x) s3=(c2.y,c2.z,c2.w)
    float accR = wt0 * c0.x + wt1 * c0.w + wt2 * c1.z + wt3 * c2.y;
    float accG = wt0 * c0.y + wt1 * c1.x + wt2 * c1.w + wt3 * c2.z;
    float accB = wt0 * c0.z + wt1 * c1.y + wt2 * c2.x + wt3 * c2.w;

    // ---- warp reduction over the 4-sample partial sums ----
    #pragma unroll
    for (int off = 16; off > 0; off >>= 1) {
        accR += __shfl_xor_sync(FULL_MASK, accR, off);
        accG += __shfl_xor_sync(FULL_MASK, accG, off);
        accB += __shfl_xor_sync(FULL_MASK, accB, off);
    }

    if (lane == 0) {
        float* o = out + (long)warp_id * 3;
        o[0] = accR;
        o[1] = accG;
        o[2] = accB;
    }
}

extern "C" void kernel_launch(void* const* d_in, const int* in_sizes, int n_in,
                              void* d_out, int out_size)
{
    const float* rgb     = (const float*)d_in[0];
    const float* density = (const float*)d_in[1];
    const float* dist    = (const float*)d_in[2];
    float* out = (float*)d_out;

    const int n_rays = in_sizes[2] / N_SAMPLES;   // distances: [N, 128]

    const int threads = 256;                       // 8 warps = 8 rays / block
    const int rays_per_block = threads / 32;
    const int blocks = (n_rays + rays_per_block - 1) / rays_per_block;

    volrend_kernel<<<blocks, threads>>>(rgb, density, dist, out, n_rays);
}

// round 16
// speedup vs baseline: 1.0129x; 1.0129x over previous
#include <cuda_runtime.h>

// Volume rendering (NeRF-style) on GB300 — FINAL (R5 config, best measured).
//
// Session evidence (DRAM% / wall us / ncu-dur us):
//   R1  strided rgb            87.8 / 98.1 / 97.4
//   R2  unit-stride rgb+smem   87.5 / 98.5 / 97.7   (access pattern irrelevant)
//   R5  R1 + __ldcs hints      88.8 / 96.3 / 96.0   <- WIN, this kernel
//   R6  2 rays/warp            89.0 / 97.0 / 95.9   (MLP depth: neutral)
//   R7  persistent dbl-buf     85.1 / 102.5 / 100.2 (occ collapse: falsified)
//   R8  2 rays + min-blocks 7  86.2 / 98.8 / 99.1   (reg squeeze de-batches loads)
//   R11 = R5 source re-run     88.2 / 97.8 / 96.8
//   R15 = R5 source re-run     88.2 / 98.0 / 96.8   (same-binary noise band)
// Conclusion: ~88.5% DRAM busy (~7.0 TB/s) is the ceiling for this 674 MB
// read-once stream (B300 path-independent LTS cap; TMA/cp.async hit the
// same cap). All structural levers tested and falsified; .cs streaming
// hints are the only reproducible win. Remaining wall spread is noise.
//
// Inputs (metadata order): rgb [N,128,3] f32, density [N,128,1] f32,
//                          distances [N,128] f32. Output: [N,3] f32.
//
// One warp per ray; 4 consecutive samples per lane.
//   delta_i  = t_{i+1} - t_i   (last sample: 1e10)
//   omega_i  = exp(-density_i * delta_i)      (= 1 - alpha_i)
//   T_i      = exclusive cumprod(omega)       (warp shfl scan)
//   weight_i = (1 - omega_i) * T_i
//   out      = sum_i weight_i * rgb_i

#ifndef FULL_MASK
#define FULL_MASK 0xffffffffu
#endif

static constexpr int N_SAMPLES = 128;
static constexpr float FAR_DELTA = 1e10f;

__global__ void __launch_bounds__(256, 8)
volrend_kernel(const float* __restrict__ rgb,
               const float* __restrict__ density,
               const float* __restrict__ dist,
               float* __restrict__ out,
               int n_rays)
{
    const int warp_id = (blockIdx.x * blockDim.x + threadIdx.x) >> 5;
    const int lane    = threadIdx.x & 31;
    if (warp_id >= n_rays) return;

    const long base = (long)warp_id * N_SAMPLES;

    // ---- coalesced streaming loads: 4 samples per lane ----
    const float4 d4 = __ldcs(reinterpret_cast<const float4*>(dist    + base) + lane);
    const float4 s4 = __ldcs(reinterpret_cast<const float4*>(density + base) + lane);
    const float4* rgb4 = reinterpret_cast<const float4*>(rgb + base * 3) + lane * 3;
    const float4 c0 = __ldcs(rgb4 + 0);
    const float4 c1 = __ldcs(rgb4 + 1);
    const float4 c2 = __ldcs(rgb4 + 2);

    // ---- deltas (next lane's first distance via shfl) ----
    const float d_next = __shfl_down_sync(FULL_MASK, d4.x, 1);
    const float dl0 = d4.y - d4.x;
    const float dl1 = d4.z - d4.y;
    const float dl2 = d4.w - d4.z;
    const float dl3 = (lane == 31) ? FAR_DELTA : (d_next - d4.w);

    // ---- omega = exp(-sigma * delta) = 1 - alpha ----
    const float w0 = __expf(-s4.x * dl0);
    const float w1 = __expf(-s4.y * dl1);
    const float w2 = __expf(-s4.z * dl2);
    const float w3 = __expf(-s4.w * dl3);

    // ---- exclusive cumprod across the warp ----
    const float p = w0 * w1 * w2 * w3;     // this lane's full product
    float incl = p;                        // inclusive scan of lane products
    #pragma unroll
    for (int off = 1; off < 32; off <<= 1) {
        const float v = __shfl_up_sync(FULL_MASK, incl, off);
        if (lane >= off) incl *= v;
    }
    float T = __shfl_up_sync(FULL_MASK, incl, 1);   // exclusive: prev lane's inclusive
    if (lane == 0) T = 1.0f;

    // ---- local weights: T walks through this lane's 4 samples ----
    const float t0 = T;
    const float t1 = t0 * w0;
    const float t2 = t1 * w1;
    const float t3 = t2 * w2;
    const float wt0 = t0 - t1;             // = alpha0 * T0
    const float wt1 = t1 - t2;
    const float wt2 = t2 - t3;
    const float wt3 = t3 * (1.0f - w3);

    // rgb layout per lane: s0=(c0.x,c0.y,c0.z) s1=(c0.w,c1.x,c1.y)
    //                      s2=(c1.z,c1.w,c2.x) s3=(c2.y,c2.z,c2.w)
    float accR = wt0 * c0.x + wt1 * c0.w + wt2 * c1.z + wt3 * c2.y;
    float accG = wt0 * c0.y + wt1 * c1.x + wt2 * c1.w + wt3 * c2.z;
    float accB = wt0 * c0.z + wt1 * c1.y + wt2 * c2.x + wt3 * c2.w;

    // ---- warp reduction over the 4-sample partial sums ----
    #pragma unroll
    for (int off = 16; off > 0; off >>= 1) {
        accR += __shfl_xor_sync(FULL_MASK, accR, off);
        accG += __shfl_xor_sync(FULL_MASK, accG, off);
        accB += __shfl_xor_sync(FULL_MASK, accB, off);
    }

    if (lane == 0) {
        float* o = out + (long)warp_id * 3;
        o[0] = accR;
        o[1] = accG;
        o[2] = accB;
    }
}

extern "C" void kernel_launch(void* const* d_in, const int* in_sizes, int n_in,
                              void* d_out, int out_size)
{
    const float* rgb     = (const float*)d_in[0];
    const float* density = (const float*)d_in[1];
    const float* dist    = (const float*)d_in[2];
    float* out = (float*)d_out;

    const int n_rays = in_sizes[2] / N_SAMPLES;   // distances: [N, 128]

    const int threads = 256;                       // 8 warps = 8 rays / block
    const int rays_per_block = threads / 32;
    const int blocks = (n_rays + rays_per_block - 1) / rays_per_block;

    volrend_kernel<<<blocks, threads>>>(rgb, density, dist, out, n_rays);
}